// round 6
// baseline (speedup 1.0000x reference)
#include <cuda_runtime.h>
#include <math.h>

// Problem constants
#define TT   2048
#define BB   32
#define ICC  512
#define HCC  512
#define LLL  2

// Recurrence kernel config
#define NCTA 128      // persistent CTAs (<=148 -> all co-resident, software grid barrier is safe)
#define CPB  4        // output channels per CTA (128*4 = 512)
#define RTH  256      // threads per CTA (8 warps)

// Projection GEMM config
#define PBM 128
#define PBN 128
#define PBK 16
#define PLD (PBM + 4) // padded smem row (272B per row stays 16B-aligned for float4 LDS)

// ---------------------------------------------------------------------------
// Scratch (static device globals: allocation-free per harness rules)
// ---------------------------------------------------------------------------
__device__ float g_xproj[(size_t)TT * BB * HCC];  // per-layer input projection (reused)
__device__ float g_ys0[(size_t)TT * BB * HCC];    // layer-0 hidden sequence (feeds layer 1)
// h state ping-pong, layout: [chan_group(=owning CTA)][batch][chan_in_group]
__device__ float g_h[2][HCC * BB];
__device__ unsigned g_cnt;                        // barrier arrive counter (self-resets to 0)
__device__ volatile unsigned g_gen;               // barrier generation (monotonic, wrap-safe)

// ---------------------------------------------------------------------------
// Software grid barrier (sense-reversing). All NCTA CTAs are co-resident
// (grid <= SM count, 1 CTA/SM), so spinning is deadlock-free. Counter returns
// to 0 after every barrier -> state is consistent across launches and graph
// replays; g_gen only needs equality comparison so wraparound is harmless.
// ---------------------------------------------------------------------------
__device__ __forceinline__ void grid_bar() {
    __syncthreads();
    if (threadIdx.x == 0) {
        unsigned g = g_gen;
        __threadfence();  // release all prior global writes of this CTA
        if (atomicAdd(&g_cnt, 1u) == NCTA - 1) {
            g_cnt = 0u;
            __threadfence();
            g_gen = g + 1u;
        } else {
            while (g_gen == g) { }
        }
        __threadfence();  // acquire (also CCTL.IVALL -> L1 invalidate on this SM)
    }
    __syncthreads();
}

// ---------------------------------------------------------------------------
// Projection GEMM: C[row, n] = sum_k A[row,k] * W[n,k] + bias[n]
// A: (T*B, 512) row-major (x or g_ys0), W: (512, 512) row-major, C -> g_xproj.
// 128x128 tile, BK=16, 256 threads, 8x8 per thread (fp32 SIMT, FMA-pipe bound).
// ---------------------------------------------------------------------------
__global__ __launch_bounds__(256, 2)
void proj_kernel(const float* __restrict__ Xin, const float* __restrict__ Wp,
                 const float* __restrict__ bp, int use_internal)
{
    const float* A = use_internal ? (const float*)g_ys0 : Xin;
    __shared__ float As[PBK][PLD];
    __shared__ float Bs[PBK][PLD];

    const int t  = threadIdx.x;
    const int m0 = blockIdx.y * PBM;
    const int n0 = blockIdx.x * PBN;
    const int lr = t >> 1;          // tile row for loading (0..127)
    const int lc = (t & 1) << 3;    // k offset for loading (0 or 8)
    const int tx = t & 15;          // n-tile coord
    const int ty = t >> 4;          // m-tile coord

    float acc[8][8];
#pragma unroll
    for (int i = 0; i < 8; i++)
#pragma unroll
        for (int j = 0; j < 8; j++) acc[i][j] = 0.f;

    const float* Ag = A  + (size_t)(m0 + lr) * ICC;
    const float* Bg = Wp + (size_t)(n0 + lr) * ICC;

    for (int k0 = 0; k0 < ICC; k0 += PBK) {
        float4 a0 = __ldg((const float4*)(Ag + k0 + lc));
        float4 a1 = __ldg((const float4*)(Ag + k0 + lc + 4));
        float4 b0 = __ldg((const float4*)(Bg + k0 + lc));
        float4 b1 = __ldg((const float4*)(Bg + k0 + lc + 4));
        As[lc+0][lr] = a0.x; As[lc+1][lr] = a0.y; As[lc+2][lr] = a0.z; As[lc+3][lr] = a0.w;
        As[lc+4][lr] = a1.x; As[lc+5][lr] = a1.y; As[lc+6][lr] = a1.z; As[lc+7][lr] = a1.w;
        Bs[lc+0][lr] = b0.x; Bs[lc+1][lr] = b0.y; Bs[lc+2][lr] = b0.z; Bs[lc+3][lr] = b0.w;
        Bs[lc+4][lr] = b1.x; Bs[lc+5][lr] = b1.y; Bs[lc+6][lr] = b1.z; Bs[lc+7][lr] = b1.w;
        __syncthreads();
#pragma unroll
        for (int k = 0; k < PBK; k++) {
            float4 am0 = *(const float4*)&As[k][ty * 8];
            float4 am1 = *(const float4*)&As[k][ty * 8 + 4];
            float4 bn0 = *(const float4*)&Bs[k][tx * 8];
            float4 bn1 = *(const float4*)&Bs[k][tx * 8 + 4];
            float am[8] = {am0.x, am0.y, am0.z, am0.w, am1.x, am1.y, am1.z, am1.w};
            float bn[8] = {bn0.x, bn0.y, bn0.z, bn0.w, bn1.x, bn1.y, bn1.z, bn1.w};
#pragma unroll
            for (int i = 0; i < 8; i++)
#pragma unroll
                for (int j = 0; j < 8; j++)
                    acc[i][j] = fmaf(am[i], bn[j], acc[i][j]);
        }
        __syncthreads();
    }

    float4 bv0 = __ldg((const float4*)(bp + n0 + tx * 8));
    float4 bv1 = __ldg((const float4*)(bp + n0 + tx * 8 + 4));
#pragma unroll
    for (int i = 0; i < 8; i++) {
        size_t row = (size_t)(m0 + ty * 8 + i);
        float4 o0 = make_float4(acc[i][0] + bv0.x, acc[i][1] + bv0.y,
                                acc[i][2] + bv0.z, acc[i][3] + bv0.w);
        float4 o1 = make_float4(acc[i][4] + bv1.x, acc[i][5] + bv1.y,
                                acc[i][6] + bv1.z, acc[i][7] + bv1.w);
        *(float4*)&g_xproj[row * HCC + n0 + tx * 8]     = o0;
        *(float4*)&g_xproj[row * HCC + n0 + tx * 8 + 4] = o1;
    }
}

// ---------------------------------------------------------------------------
// Recurrence: h_new[b,o] = tanh(xproj[t,b,o] + sum_i h[b,i]*Wh[o,i] + bh[o])
// Persistent kernel: CTA bid owns channels [4*bid, 4*bid+4). Wh slice lives
// in smem for all 2048 steps. Thread (lane=b, warp=k-slice of 64) reads its
// h chunk directly from L2 (__ldcg float4, each element consumed exactly once,
// fully coalesced thanks to the grouped h layout). 8-way k-partials reduced
// through smem, 128 threads do the tanh epilogue + h/ys writes, then grid bar.
// ---------------------------------------------------------------------------
__global__ __launch_bounds__(RTH, 1)
void rec_kernel(const float* __restrict__ Wh, const float* __restrict__ bh,
                float* __restrict__ out_ys, float* __restrict__ out_hs,
                int write_internal)
{
    __shared__ float w_s[CPB * HCC];     // 8 KB: Wh rows for this CTA's 4 channels
    __shared__ float red[8 * BB * CPB];  // 4 KB: k-split partials [warp][b][c]

    const int t    = threadIdx.x;
    const int bid  = blockIdx.x;
    const int ci0  = bid * CPB;
    const int lane = t & 31;             // batch index
    const int warp = t >> 5;             // k-slice (64 wide)
    const int i0   = warp * 64;

    float* ysp = write_internal ? (float*)g_ys0 : out_ys;

    // Load Wh slice (2048 contiguous floats) into smem once.
    {
        const float4* src = (const float4*)(Wh + (size_t)ci0 * HCC);
        float4* dst = (float4*)w_s;
        dst[t]       = __ldg(src + t);
        dst[t + 256] = __ldg(src + t + 256);
    }
    // Zero h state buffer 0 (each CTA zeros its own 128-float slice).
    if (t < 128) g_h[0][bid * 128 + t] = 0.f;

    const int eb = t >> 2;   // epilogue batch
    const int ec = t & 3;    // epilogue channel-in-group
    float bhv = 0.f;
    if (t < 128) bhv = __ldg(bh + ci0 + ec);

    grid_bar();  // h[0] zeroed + visible everywhere

    for (int s = 0; s < TT; s++) {
        const int cur = s & 1;

        // Prefetch this step's xproj early (hides DRAM latency behind the dot).
        float xpv = 0.f;
        if (t < 128)
            xpv = __ldg(&g_xproj[(size_t)s * (BB * HCC) + (size_t)eb * HCC + ci0 + ec]);

        const float* hb = g_h[cur];
        float a0 = 0.f, a1 = 0.f, a2 = 0.f, a3 = 0.f;
#pragma unroll
        for (int i = 0; i < 64; i += 4) {
            // h[i0+i .. i0+i+3][lane] packed as one float4 in the grouped layout
            float4 hv = __ldcg((const float4*)(hb + (i0 + i) * 32 + lane * 4));
            float4 w0 = *(const float4*)&w_s[0 * HCC + i0 + i];
            float4 w1 = *(const float4*)&w_s[1 * HCC + i0 + i];
            float4 w2 = *(const float4*)&w_s[2 * HCC + i0 + i];
            float4 w3 = *(const float4*)&w_s[3 * HCC + i0 + i];
            a0 = fmaf(w0.x, hv.x, a0); a0 = fmaf(w0.y, hv.y, a0);
            a0 = fmaf(w0.z, hv.z, a0); a0 = fmaf(w0.w, hv.w, a0);
            a1 = fmaf(w1.x, hv.x, a1); a1 = fmaf(w1.y, hv.y, a1);
            a1 = fmaf(w1.z, hv.z, a1); a1 = fmaf(w1.w, hv.w, a1);
            a2 = fmaf(w2.x, hv.x, a2); a2 = fmaf(w2.y, hv.y, a2);
            a2 = fmaf(w2.z, hv.z, a2); a2 = fmaf(w2.w, hv.w, a2);
            a3 = fmaf(w3.x, hv.x, a3); a3 = fmaf(w3.y, hv.y, a3);
            a3 = fmaf(w3.z, hv.z, a3); a3 = fmaf(w3.w, hv.w, a3);
        }
        *(float4*)&red[warp * 128 + lane * 4] = make_float4(a0, a1, a2, a3);
        __syncthreads();

        if (t < 128) {
            float sum = xpv + bhv;
#pragma unroll
            for (int w = 0; w < 8; w++) sum += red[w * 128 + eb * 4 + ec];
            float hn = tanhf(sum);
            ysp[(size_t)s * (BB * HCC) + (size_t)eb * HCC + ci0 + ec] = hn;
            // grouped layout write: fully coalesced (lanes 0..31 -> consecutive)
            g_h[cur ^ 1][bid * 128 + eb * 4 + ec] = hn;
            if (s == TT - 1) out_hs[eb * HCC + ci0 + ec] = hn;
        }
        grid_bar();  // publish h_new chip-wide before next step reads it
    }
}

// ---------------------------------------------------------------------------
// Launch: proj(L0) -> rec(L0, ys->g_ys0, hT->out[0:16384])
//         proj(L1 from g_ys0) -> rec(L1, ys->out[32768:], hT->out[16384:32768])
// Output layout: [hs (L,B,HC) | inp (T,B,HC)]
// ---------------------------------------------------------------------------
extern "C" void kernel_launch(void* const* d_in, const int* in_sizes, int n_in,
                              void* d_out, int out_size) {
    const float* x  = (const float*)d_in[0];
    const float* Wi = (const float*)d_in[1];
    const float* bi = (const float*)d_in[2];
    const float* Wh = (const float*)d_in[3];
    const float* bh = (const float*)d_in[4];
    float* out = (float*)d_out;

    dim3 pg(HCC / PBN, (TT * BB) / PBM);  // (4, 512)

    // Layer 0
    proj_kernel<<<pg, 256>>>(x, Wi, bi, 0);
    rec_kernel<<<NCTA, RTH>>>(Wh, bh, nullptr, out, 1);

    // Layer 1
    proj_kernel<<<pg, 256>>>(x, Wi + HCC * ICC, bi + HCC, 1);
    rec_kernel<<<NCTA, RTH>>>(Wh + HCC * HCC, bh + HCC,
                              out + (size_t)LLL * BB * HCC,  // inp region
                              out + BB * HCC,                // hs[1]
                              0);
}